// round 2
// baseline (speedup 1.0000x reference)
#include <cuda_runtime.h>
#include <math.h>

#define D 8192
#define M_TIME 16
#define RMS_EPS 1e-6f
#define DEN_EPS 1e-9f
#define KTOP 1024   // D/8
#define RPB 4       // rows per block in matvec kernels

// Scratch (no allocations allowed)
__device__ __align__(16) float g_x[D];
__device__ __align__(16) float g_r[D];
__device__ __align__(16) float g_k[D];
__device__ __align__(16) float g_v[D];
__device__ __align__(16) float g_y[D];
__device__ __align__(16) float g_h[D];
__device__ unsigned g_cnt = 0;

__device__ __forceinline__ float warp_sum(float v) {
    #pragma unroll
    for (int o = 16; o > 0; o >>= 1) v += __shfl_down_sync(0xffffffffu, v, o);
    return v;
}

// ---------------------------------------------------------------------------
// K1: x = rmsnorm(x_in + pred) * norm_w      (1 block, 1024 threads)
// ---------------------------------------------------------------------------
__global__ void k_rms(const float* __restrict__ x_in,
                      const float* __restrict__ pred,
                      const float* __restrict__ norm_w) {
    __shared__ float sh[32];
    __shared__ float s_inv;
    const int t = threadIdx.x;  // 1024
    float vals[8];
    float acc = 0.f;
    #pragma unroll
    for (int j = 0; j < 8; j++) {
        int i = t + j * 1024;
        float a = x_in[i] + pred[i];
        vals[j] = a;
        acc = fmaf(a, a, acc);
    }
    acc = warp_sum(acc);
    const int lane = t & 31, wid = t >> 5;
    if (lane == 0) sh[wid] = acc;
    __syncthreads();
    if (wid == 0) {
        float v = sh[lane];
        v = warp_sum(v);
        if (lane == 0) s_inv = rsqrtf(v * (1.0f / D) + RMS_EPS);
    }
    __syncthreads();
    const float inv = s_inv;
    #pragma unroll
    for (int j = 0; j < 8; j++) {
        int i = t + j * 1024;
        g_x[i] = vals[j] * inv * norm_w[i];
    }
}

// ---------------------------------------------------------------------------
// K2: r = sigmoid(Wr@x), k = Wk@x, v = Wv@x   (3*2048 blocks, 256 threads,
//     4 rows/block). Last finishing block also computes the gate -> y.
// ---------------------------------------------------------------------------
__global__ void __launch_bounds__(256) k_mv3(const float* __restrict__ Wr,
                                             const float* __restrict__ Wk,
                                             const float* __restrict__ Wv,
                                             const float* __restrict__ state_num,
                                             const float* __restrict__ state_den,
                                             const float* __restrict__ decay_param,
                                             const float* __restrict__ W_time,
                                             const float* __restrict__ step_pos,
                                             const int*   __restrict__ dt) {
    const int bid = blockIdx.x;
    const int mat = bid / (D / RPB);              // 0..2
    const int row0 = (bid % (D / RPB)) * RPB;
    const float* W = (mat == 0 ? Wr : (mat == 1 ? Wk : Wv));
    const float4* __restrict__ W4 = (const float4*)(W + (size_t)row0 * D);
    const float4* __restrict__ X4 = (const float4*)g_x;
    const int t = threadIdx.x;

    float a0 = 0.f, a1 = 0.f, a2 = 0.f, a3 = 0.f;
    #pragma unroll
    for (int j = 0; j < D / 4 / 256; j++) {       // 8 iterations
        int idx = t + j * 256;
        float4 x  = X4[idx];
        float4 w0 = __ldcs(W4 + idx);
        float4 w1 = __ldcs(W4 + 1 * (D / 4) + idx);
        float4 w2 = __ldcs(W4 + 2 * (D / 4) + idx);
        float4 w3 = __ldcs(W4 + 3 * (D / 4) + idx);
        a0 = fmaf(w0.x, x.x, fmaf(w0.y, x.y, fmaf(w0.z, x.z, fmaf(w0.w, x.w, a0))));
        a1 = fmaf(w1.x, x.x, fmaf(w1.y, x.y, fmaf(w1.z, x.z, fmaf(w1.w, x.w, a1))));
        a2 = fmaf(w2.x, x.x, fmaf(w2.y, x.y, fmaf(w2.z, x.z, fmaf(w2.w, x.w, a2))));
        a3 = fmaf(w3.x, x.x, fmaf(w3.y, x.y, fmaf(w3.z, x.z, fmaf(w3.w, x.w, a3))));
    }

    __shared__ float sh[RPB][8];
    a0 = warp_sum(a0); a1 = warp_sum(a1); a2 = warp_sum(a2); a3 = warp_sum(a3);
    const int lane = t & 31, wid = t >> 5;
    if (lane == 0) { sh[0][wid] = a0; sh[1][wid] = a1; sh[2][wid] = a2; sh[3][wid] = a3; }
    __syncthreads();
    if (t < RPB) {
        float s = sh[t][0];
        #pragma unroll
        for (int i = 1; i < 8; i++) s += sh[t][i];
        int row = row0 + t;
        if (mat == 0)      g_r[row] = 1.0f / (1.0f + __expf(-s));
        else if (mat == 1) g_k[row] = s;
        else               g_v[row] = s;
    }

    // ---- last-block gate fusion ----
    __threadfence();
    __shared__ unsigned s_rank;
    if (t == 0) s_rank = atomicAdd(&g_cnt, 1u);
    __syncthreads();
    if (s_rank == gridDim.x - 1) {
        if (t == 0) g_cnt = 0;          // reset for next graph replay
        __threadfence();
        const int n = dt[0];
        const float sp = step_pos[0];
        #pragma unroll
        for (int j = 0; j < D / 256; j++) {       // 32 elems/thread
            int i = t + j * 256;
            float sg = 1.0f / (1.0f + expf(-decay_param[i]));
            float lam = sg * sg;
            float mul = 1.0f;
            for (int q = 0; q < n; q++) mul *= lam;

            float v = g_v[i];
            if (i < 2 * M_TIME) {
                int p = i >> 1;
                float th = sp * W_time[p];
                float c, sn_;
                sincosf(th, &sn_, &c);
                float v0 = g_v[2 * p];
                float v1 = g_v[2 * p + 1];
                v = (i & 1) ? (v0 * sn_ + v1 * c) : (v0 * c - v1 * sn_);
            }
            float w = expf(g_k[i]);
            float num = state_num[i] * mul * lam + w * v;
            float den = state_den[i] * mul * lam + w;
            g_y[i] = g_r[i] * (num / (den + DEN_EPS));
        }
    }
}

// ---------------------------------------------------------------------------
// K3: h = x + Wo@y                           (2048 blocks, 256 threads, 4 rows)
// ---------------------------------------------------------------------------
__global__ void __launch_bounds__(256) k_mv_o(const float* __restrict__ Wo) {
    const int row0 = blockIdx.x * RPB;
    const float4* __restrict__ W4 = (const float4*)(Wo + (size_t)row0 * D);
    const float4* __restrict__ Y4 = (const float4*)g_y;
    const int t = threadIdx.x;

    float a0 = 0.f, a1 = 0.f, a2 = 0.f, a3 = 0.f;
    #pragma unroll
    for (int j = 0; j < D / 4 / 256; j++) {
        int idx = t + j * 256;
        float4 y  = Y4[idx];
        float4 w0 = __ldcs(W4 + idx);
        float4 w1 = __ldcs(W4 + 1 * (D / 4) + idx);
        float4 w2 = __ldcs(W4 + 2 * (D / 4) + idx);
        float4 w3 = __ldcs(W4 + 3 * (D / 4) + idx);
        a0 = fmaf(w0.x, y.x, fmaf(w0.y, y.y, fmaf(w0.z, y.z, fmaf(w0.w, y.w, a0))));
        a1 = fmaf(w1.x, y.x, fmaf(w1.y, y.y, fmaf(w1.z, y.z, fmaf(w1.w, y.w, a1))));
        a2 = fmaf(w2.x, y.x, fmaf(w2.y, y.y, fmaf(w2.z, y.z, fmaf(w2.w, y.w, a2))));
        a3 = fmaf(w3.x, y.x, fmaf(w3.y, y.y, fmaf(w3.z, y.z, fmaf(w3.w, y.w, a3))));
    }

    __shared__ float sh[RPB][8];
    a0 = warp_sum(a0); a1 = warp_sum(a1); a2 = warp_sum(a2); a3 = warp_sum(a3);
    const int lane = t & 31, wid = t >> 5;
    if (lane == 0) { sh[0][wid] = a0; sh[1][wid] = a1; sh[2][wid] = a2; sh[3][wid] = a3; }
    __syncthreads();
    if (t < RPB) {
        float s = sh[t][0];
        #pragma unroll
        for (int i = 1; i < 8; i++) s += sh[t][i];
        int row = row0 + t;
        g_h[row] = g_x[row] + s;
    }
}

// ---------------------------------------------------------------------------
// K4: kWTA — exact k-th largest |h| via 4x8-bit radix select, then threshold
//     (1 block, 1024 threads)
// ---------------------------------------------------------------------------
__global__ void k_kwta(float* __restrict__ out) {
    __shared__ unsigned hist[256];
    __shared__ unsigned s_prefix, s_k;
    const int t = threadIdx.x;  // 1024

    unsigned bits[8];
    #pragma unroll
    for (int j = 0; j < 8; j++)
        bits[j] = __float_as_uint(fabsf(g_h[t + j * 1024]));

    unsigned prefix = 0;
    unsigned kk = KTOP;
    #pragma unroll
    for (int shift = 24; shift >= 0; shift -= 8) {
        if (t < 256) hist[t] = 0;
        __syncthreads();
        unsigned mask = (shift == 24) ? 0u : (~0u << (shift + 8));
        #pragma unroll
        for (int j = 0; j < 8; j++) {
            if ((bits[j] & mask) == prefix)
                atomicAdd(&hist[(bits[j] >> shift) & 255u], 1u);
        }
        __syncthreads();
        if (t == 0) {
            unsigned cum = 0;
            int b = 255;
            for (; b > 0; b--) {
                if (cum + hist[b] >= kk) break;
                cum += hist[b];
            }
            s_prefix = prefix | ((unsigned)b << shift);
            s_k = kk - cum;
        }
        __syncthreads();
        prefix = s_prefix;
        kk = s_k;
        __syncthreads();
    }

    const float thr = __uint_as_float(prefix);
    #pragma unroll
    for (int j = 0; j < 8; j++) {
        int i = t + j * 1024;
        float h = g_h[i];
        out[i] = (fabsf(h) >= thr) ? h : 0.0f;
    }
}

// ---------------------------------------------------------------------------
extern "C" void kernel_launch(void* const* d_in, const int* in_sizes, int n_in,
                              void* d_out, int out_size) {
    const float* x_in        = (const float*)d_in[0];
    const float* state_num   = (const float*)d_in[1];
    const float* state_den   = (const float*)d_in[2];
    const float* pred        = (const float*)d_in[3];
    const float* norm_w      = (const float*)d_in[4];
    const float* Wr          = (const float*)d_in[5];
    const float* Wk          = (const float*)d_in[6];
    const float* Wv          = (const float*)d_in[7];
    const float* Wo          = (const float*)d_in[8];
    const float* decay_param = (const float*)d_in[9];
    const float* W_time      = (const float*)d_in[10];
    const float* step_pos    = (const float*)d_in[11];
    const int*   dt          = (const int*)d_in[12];
    float* out = (float*)d_out;

    k_rms<<<1, 1024>>>(x_in, pred, norm_w);
    k_mv3<<<3 * (D / RPB), 256>>>(Wr, Wk, Wv, state_num, state_den,
                                  decay_param, W_time, step_pos, dt);
    k_mv_o<<<D / RPB, 256>>>(Wo);
    k_kwta<<<1, 1024>>>(out);
}

// round 3
// speedup vs baseline: 1.2568x; 1.2568x over previous
#include <cuda_runtime.h>
#include <math.h>

#define D 8192
#define M_TIME 16
#define RMS_EPS 1e-6f
#define DEN_EPS 1e-9f
#define KTOP 1024  // D/8

// Scratch (no allocations allowed)
__device__ __align__(16) float g_x[D];
__device__ __align__(16) float g_r[D];
__device__ __align__(16) float g_k[D];
__device__ __align__(16) float g_v[D];
__device__ __align__(16) float g_y[D];
__device__ __align__(16) float g_h[D];

__device__ __forceinline__ float warp_sum(float v) {
    #pragma unroll
    for (int o = 16; o > 0; o >>= 1) v += __shfl_down_sync(0xffffffffu, v, o);
    return v;
}

// ---------------------------------------------------------------------------
// K1: x = rmsnorm(x_in + pred) * norm_w      (1 block, 1024 threads)
// ---------------------------------------------------------------------------
__global__ void k_rms(const float* __restrict__ x_in,
                      const float* __restrict__ pred,
                      const float* __restrict__ norm_w) {
    __shared__ float sh[32];
    __shared__ float s_inv;
    const int t = threadIdx.x;  // 1024
    float vals[8];
    float acc = 0.f;
    #pragma unroll
    for (int j = 0; j < 8; j++) {
        int i = t + j * 1024;
        float a = x_in[i] + pred[i];
        vals[j] = a;
        acc = fmaf(a, a, acc);
    }
    acc = warp_sum(acc);
    const int lane = t & 31, wid = t >> 5;
    if (lane == 0) sh[wid] = acc;
    __syncthreads();
    if (wid == 0) {
        float v = sh[lane];
        v = warp_sum(v);
        if (lane == 0) s_inv = rsqrtf(v * (1.0f / D) + RMS_EPS);
    }
    __syncthreads();
    const float inv = s_inv;
    #pragma unroll
    for (int j = 0; j < 8; j++) {
        int i = t + j * 1024;
        g_x[i] = vals[j] * inv * norm_w[i];
    }
}

// ---------------------------------------------------------------------------
// K2: r = sigmoid(Wr@x), k = Wk@x, v = Wv@x   (3*8192 blocks, 256 threads)
// ---------------------------------------------------------------------------
__global__ void __launch_bounds__(256) k_mv3(const float* __restrict__ Wr,
                                             const float* __restrict__ Wk,
                                             const float* __restrict__ Wv) {
    const int bid = blockIdx.x;
    const int mat = bid >> 13;           // 0..2
    const int row = bid & (D - 1);
    const float* W = (mat == 0 ? Wr : (mat == 1 ? Wk : Wv)) + (size_t)row * D;
    const float4* __restrict__ W4 = (const float4*)W;
    const float4* __restrict__ X4 = (const float4*)g_x;

    const int t = threadIdx.x;
    float acc = 0.f;
    #pragma unroll
    for (int j = 0; j < D / 4 / 256; j++) {  // 8 iterations
        int idx = t + j * 256;
        float4 w = W4[idx];
        float4 x = X4[idx];
        acc = fmaf(w.x, x.x, acc);
        acc = fmaf(w.y, x.y, acc);
        acc = fmaf(w.z, x.z, acc);
        acc = fmaf(w.w, x.w, acc);
    }
    __shared__ float sh[8];
    acc = warp_sum(acc);
    const int lane = t & 31, wid = t >> 5;
    if (lane == 0) sh[wid] = acc;
    __syncthreads();
    if (t == 0) {
        float s = sh[0];
        #pragma unroll
        for (int i = 1; i < 8; i++) s += sh[i];
        if (mat == 0)      g_r[row] = 1.0f / (1.0f + __expf(-s));
        else if (mat == 1) g_k[row] = s;
        else               g_v[row] = s;
    }
}

// ---------------------------------------------------------------------------
// K3: decay/RoPE/gating -> y                 (32 blocks, 256 threads)
// ---------------------------------------------------------------------------
__global__ void k_gate(const float* __restrict__ state_num,
                       const float* __restrict__ state_den,
                       const float* __restrict__ decay_param,
                       const float* __restrict__ W_time,
                       const float* __restrict__ step_pos,
                       const int*   __restrict__ dt) {
    const int i = blockIdx.x * blockDim.x + threadIdx.x;
    if (i >= D) return;

    float s = 1.0f / (1.0f + expf(-decay_param[i]));
    float lam = s * s;
    float mul = 1.0f;
    int n = dt[0];
    for (int j = 0; j < n; j++) mul *= lam;

    float v = g_v[i];
    if (i < 2 * M_TIME) {
        int p = i >> 1;
        float th = step_pos[0] * W_time[p];
        float c, sn_;
        sincosf(th, &sn_, &c);
        float v0 = g_v[2 * p];
        float v1 = g_v[2 * p + 1];
        v = (i & 1) ? (v0 * sn_ + v1 * c) : (v0 * c - v1 * sn_);
    }

    float w = expf(g_k[i]);
    float num = state_num[i] * mul * lam + w * v;
    float den = state_den[i] * mul * lam + w;
    g_y[i] = g_r[i] * (num / (den + DEN_EPS));
}

// ---------------------------------------------------------------------------
// K4: h = x + Wo@y                           (8192 blocks, 256 threads)
// ---------------------------------------------------------------------------
__global__ void __launch_bounds__(256) k_mv_o(const float* __restrict__ Wo) {
    const int row = blockIdx.x;
    const float4* __restrict__ W4 = (const float4*)(Wo + (size_t)row * D);
    const float4* __restrict__ Y4 = (const float4*)g_y;

    const int t = threadIdx.x;
    float acc = 0.f;
    #pragma unroll
    for (int j = 0; j < D / 4 / 256; j++) {
        int idx = t + j * 256;
        float4 w = W4[idx];
        float4 y = Y4[idx];
        acc = fmaf(w.x, y.x, acc);
        acc = fmaf(w.y, y.y, acc);
        acc = fmaf(w.z, y.z, acc);
        acc = fmaf(w.w, y.w, acc);
    }
    __shared__ float sh[8];
    acc = warp_sum(acc);
    const int lane = t & 31, wid = t >> 5;
    if (lane == 0) sh[wid] = acc;
    __syncthreads();
    if (t == 0) {
        float s = sh[0];
        #pragma unroll
        for (int i = 1; i < 8; i++) s += sh[i];
        g_h[row] = g_x[row] + s;
    }
}

// ---------------------------------------------------------------------------
// K5: kWTA — exact k-th largest |h| via 4x8-bit radix select with PARALLEL
//     suffix-scan bucket selection, then threshold. (1 block, 1024 threads)
// ---------------------------------------------------------------------------
__global__ void k_kwta(float* __restrict__ out) {
    __shared__ unsigned hist[256];
    __shared__ unsigned wsum[8];
    __shared__ unsigned s_prefix, s_k;
    const int t = threadIdx.x;  // 1024
    const int lane = t & 31, wid = t >> 5;

    unsigned bits[8];
    #pragma unroll
    for (int j = 0; j < 8; j++)
        bits[j] = __float_as_uint(fabsf(g_h[t + j * 1024]));

    unsigned prefix = 0;
    unsigned kk = KTOP;
    #pragma unroll
    for (int shift = 24; shift >= 0; shift -= 8) {
        if (t < 256) hist[t] = 0;
        __syncthreads();
        unsigned mask = (shift == 24) ? 0u : (~0u << (shift + 8));
        #pragma unroll
        for (int j = 0; j < 8; j++) {
            if ((bits[j] & mask) == prefix)
                atomicAdd(&hist[(bits[j] >> shift) & 255u], 1u);
        }
        __syncthreads();
        if (t < 256) {
            // Inclusive suffix sum S[t] = sum_{i>=t} hist[i] over 256 buckets.
            unsigned h = hist[t];
            unsigned v = h;
            #pragma unroll
            for (int o = 1; o < 32; o <<= 1) {
                unsigned u = __shfl_down_sync(0xffffffffu, v, o);
                if (lane + o < 32) v += u;
            }
            if (lane == 0) wsum[wid] = v;   // warp suffix totals
            __syncwarp();
        }
        __syncthreads();
        if (t < 256) {
            unsigned hi = 0;
            #pragma unroll
            for (int w = 0; w < 8; w++)
                if (w > wid) hi += wsum[w];
            // recompute warp-local inclusive suffix
            unsigned h = hist[t];
            unsigned v = h;
            #pragma unroll
            for (int o = 1; o < 32; o <<= 1) {
                unsigned u = __shfl_down_sync(0xffffffffu, v, o);
                if (lane + o < 32) v += u;
            }
            unsigned S = v + hi;            // S[t]
            // unique bucket: S[t] >= kk and S[t] - hist[t] < kk
            if (S >= kk && (S - h) < kk) {
                s_prefix = prefix | ((unsigned)t << shift);
                s_k = kk - (S - h);
            }
        }
        __syncthreads();
        prefix = s_prefix;
        kk = s_k;
        __syncthreads();
    }

    const float thr = __uint_as_float(prefix);
    #pragma unroll
    for (int j = 0; j < 8; j++) {
        int i = t + j * 1024;
        float h = g_h[i];
        out[i] = (fabsf(h) >= thr) ? h : 0.0f;
    }
}

// ---------------------------------------------------------------------------
extern "C" void kernel_launch(void* const* d_in, const int* in_sizes, int n_in,
                              void* d_out, int out_size) {
    const float* x_in        = (const float*)d_in[0];
    const float* state_num   = (const float*)d_in[1];
    const float* state_den   = (const float*)d_in[2];
    const float* pred        = (const float*)d_in[3];
    const float* norm_w      = (const float*)d_in[4];
    const float* Wr          = (const float*)d_in[5];
    const float* Wk          = (const float*)d_in[6];
    const float* Wv          = (const float*)d_in[7];
    const float* Wo          = (const float*)d_in[8];
    const float* decay_param = (const float*)d_in[9];
    const float* W_time      = (const float*)d_in[10];
    const float* step_pos    = (const float*)d_in[11];
    const int*   dt          = (const int*)d_in[12];
    float* out = (float*)d_out;

    k_rms<<<1, 1024>>>(x_in, pred, norm_w);
    k_mv3<<<3 * D, 256>>>(Wr, Wk, Wv);
    k_gate<<<D / 256, 256>>>(state_num, state_den, decay_param, W_time, step_pos, dt);
    k_mv_o<<<D, 256>>>(Wo);
    k_kwta<<<1, 1024>>>(out);
}